// round 3
// baseline (speedup 1.0000x reference)
#include <cuda_runtime.h>
#include <cstdint>

// Problem constants
#define OUT_N 11008
#define IN_K  4096
#define GS    128
#define NG    32          // groups per row
#define M_TOK 8

// Tiling
#define BLOCK            256
#define WARPS            8
#define T_ROWS           2                      // output rows per warp
#define ROWS_PER_BLOCK   (WARPS * T_ROWS)       // 16 -> grid 688
#define CHUNK            1024                   // k-columns of x staged in smem
#define GPC              (CHUNK / GS)           // 8 groups per chunk
#define NCHUNK           (IN_K / CHUNK)         // 4
#define DIST             4                      // weight prefetch distance (groups)

typedef unsigned long long u64;

// ---- packed f32x2 helpers (Blackwell FFMA2 path; ptxas won't emit from C++) ----
__device__ __forceinline__ u64 pkf(float lo, float hi) {
    u64 r; asm("mov.b64 %0, {%1, %2};" : "=l"(r) : "f"(lo), "f"(hi)); return r;
}
__device__ __forceinline__ u64 pki(unsigned lo, unsigned hi) {
    u64 r; asm("mov.b64 %0, {%1, %2};" : "=l"(r) : "r"(lo), "r"(hi)); return r;
}
__device__ __forceinline__ u64 add2(u64 a, u64 b) {
    u64 r; asm("add.rn.f32x2 %0, %1, %2;" : "=l"(r) : "l"(a), "l"(b)); return r;
}
__device__ __forceinline__ u64 mul2(u64 a, u64 b) {
    u64 r; asm("mul.rn.f32x2 %0, %1, %2;" : "=l"(r) : "l"(a), "l"(b)); return r;
}
__device__ __forceinline__ u64 fma2(u64 a, u64 b, u64 c) {
    u64 r; asm("fma.rn.f32x2 %0, %1, %2, %3;" : "=l"(r) : "l"(a), "l"(b), "l"(c)); return r;
}
__device__ __forceinline__ float2 upk(u64 a) {
    float lo, hi; asm("mov.b64 {%0, %1}, %2;" : "=f"(lo), "=f"(hi) : "l"(a));
    return make_float2(lo, hi);
}

__global__ void __launch_bounds__(BLOCK, 2)
qlinear_pergrp_kernel(const float* __restrict__ x,
                      const int*   __restrict__ qw,
                      const int*   __restrict__ qz,
                      const float* __restrict__ sc,
                      float*       __restrict__ out)
{
    // x chunk, [m][k/4] float4: lane loads contiguous 16B -> conflict-free LDS.128
    __shared__ float4 xs4[M_TOK][CHUNK / 4];          // 32 KB
    // per (local row, group): {s, s, -(z+2^23), -(z+2^23)} pre-duplicated for f32x2
    __shared__ float4 szp[ROWS_PER_BLOCK][NG];        // 8 KB

    const int tid  = threadIdx.x;
    const int warp = tid >> 5;
    const int lane = tid & 31;
    const int row_blk = blockIdx.x * ROWS_PER_BLOCK;

    // ---- precompute per-group constants (duplicated halves) ----
    for (int e = tid; e < ROWS_PER_BLOCK * NG; e += BLOCK) {
        const int lr = e >> 5;
        const int g  = e & (NG - 1);
        const int gr = row_blk + lr;
        const float s  = sc[gr * NG + g];
        const float nz = -((float)qz[gr * NG + g] + 8388608.0f);  // -(z + 2^23), exact
        szp[lr][g] = make_float4(s, s, nz, nz);
    }
    // (first chunk's __syncthreads covers szp visibility)

    const int row0 = row_blk + warp * T_ROWS;
    const int4* q0 = (const int4*)(qw + (size_t)row0 * IN_K);
    const int4* q1 = q0 + (IN_K / 4);

    u64 acc[T_ROWS][M_TOK];
#pragma unroll
    for (int r = 0; r < T_ROWS; r++)
#pragma unroll
        for (int m = 0; m < M_TOK; m++) acc[r][m] = 0ULL;

    // ---- rolling prefetch, distance DIST=4 groups (8 LDG.128 in flight) ----
    int4 buf[DIST][T_ROWS];
#pragma unroll
    for (int d = 0; d < DIST; d++) {
        buf[d][0] = __ldcs(q0 + d * 32 + lane);
        buf[d][1] = __ldcs(q1 + d * 32 + lane);
    }

    const float4* xg = (const float4*)x;

    for (int c = 0; c < NCHUNK; c++) {
        __syncthreads();
        // cooperative x chunk load: 2048 float4, fully coalesced (x is L2-resident)
#pragma unroll
        for (int it = 0; it < (M_TOK * (CHUNK / 4)) / BLOCK; it++) {
            const int idx = it * BLOCK + tid;
            const int m  = idx >> 8;
            const int i4 = idx & 255;
            xs4[m][i4] = xg[m * (IN_K / 4) + c * (CHUNK / 4) + i4];
        }
        __syncthreads();

#pragma unroll
        for (int jj = 0; jj < GPC; jj++) {
            const int g  = c * GPC + jj;
            const int bi = jj & (DIST - 1);       // static buffer slot (DIST | GPC)

            // grab current weights, then immediately refill slot with group g+DIST
            const int4 w0 = buf[bi][0];
            const int4 w1 = buf[bi][1];
            const int gn = g + DIST;
            if (gn < NG) {
                const int off = gn * 32 + lane;
                buf[bi][0] = __ldcs(q0 + off);
                buf[bi][1] = __ldcs(q1 + off);
            }

            // dequant both rows (k-packed f32x2); exact:
            // as_float(q | 0x4B000000) == 2^23 + q ; (2^23+q) + (-(2^23+z)) is Sterbenz-exact
            const float4 sz0 = szp[warp * T_ROWS + 0][g];   // uniform broadcast
            const float4 sz1 = szp[warp * T_ROWS + 1][g];
            const u64 ss0 = pkf(sz0.x, sz0.y), zz0 = pkf(sz0.z, sz0.w);
            const u64 ss1 = pkf(sz1.x, sz1.y), zz1 = pkf(sz1.z, sz1.w);

            const u64 a01 = mul2(add2(pki((unsigned)w0.x | 0x4B000000u,
                                          (unsigned)w0.y | 0x4B000000u), zz0), ss0);
            const u64 a23 = mul2(add2(pki((unsigned)w0.z | 0x4B000000u,
                                          (unsigned)w0.w | 0x4B000000u), zz0), ss0);
            const u64 b01 = mul2(add2(pki((unsigned)w1.x | 0x4B000000u,
                                          (unsigned)w1.y | 0x4B000000u), zz1), ss1);
            const u64 b23 = mul2(add2(pki((unsigned)w1.z | 0x4B000000u,
                                          (unsigned)w1.w | 0x4B000000u), zz1), ss1);

            // stream x per token to keep register liveness low
#pragma unroll
            for (int m = 0; m < M_TOK; m++) {
                const float4 xv = xs4[m][jj * 32 + lane];   // LDS.128
                const u64 x01 = pkf(xv.x, xv.y);            // adjacent regs -> free pair
                const u64 x23 = pkf(xv.z, xv.w);
                acc[0][m] = fma2(a01, x01, acc[0][m]);
                acc[0][m] = fma2(a23, x23, acc[0][m]);
                acc[1][m] = fma2(b01, x01, acc[1][m]);
                acc[1][m] = fma2(b23, x23, acc[1][m]);
            }
        }
    }

    // ---- fold f32x2 halves, then intra-warp reduction over the k-split ----
#pragma unroll
    for (int r = 0; r < T_ROWS; r++)
#pragma unroll
        for (int m = 0; m < M_TOK; m++) {
            const float2 v = upk(acc[r][m]);
            float s = v.x + v.y;
#pragma unroll
            for (int off = 16; off > 0; off >>= 1)
                s += __shfl_xor_sync(0xffffffffu, s, off);
            if (lane == 0)
                out[m * OUT_N + (row0 + r)] = s;
        }
}

extern "C" void kernel_launch(void* const* d_in, const int* in_sizes, int n_in,
                              void* d_out, int out_size)
{
    const float* x  = (const float*)d_in[0];   // [8, 4096] f32
    const int*   qw = (const int*)  d_in[1];   // [11008, 4096] int32 in [0,15]
    const int*   qz = (const int*)  d_in[2];   // [11008, 32] int32
    const float* sc = (const float*)d_in[3];   // [11008, 32] f32
    float* out = (float*)d_out;                // [8, 11008] f32

    const int grid = OUT_N / ROWS_PER_BLOCK;   // 688
    qlinear_pergrp_kernel<<<grid, BLOCK>>>(x, qw, qz, sc, out);
}